// round 12
// baseline (speedup 1.0000x reference)
#include <cuda_runtime.h>
#include <cstdint>

#define NN     512
#define FIN    256
#define HF     256
#define NH     8
#define NF     32
#define NB     4
#define ITILE  32    // i-rows per item
#define GLS    36
#define GRS    36
#define ATS    36

typedef unsigned long long ull;

__device__ float g_scratch[(size_t)NB * NN * 512];
__device__ unsigned g_ctr = 0;

// ---- packed f32x2 helpers -------------------------------------------------
__device__ __forceinline__ ull pack2(float lo, float hi) {
    ull r; asm("mov.b64 %0, {%1, %2};" : "=l"(r) : "f"(lo), "f"(hi)); return r;
}
__device__ __forceinline__ void unpack2(ull v, float& lo, float& hi) {
    asm("mov.b64 {%0, %1}, %2;" : "=f"(lo), "=f"(hi) : "l"(v));
}
__device__ __forceinline__ ull add2(ull a, ull b) {
    ull r; asm("add.rn.f32x2 %0, %1, %2;" : "=l"(r) : "l"(a), "l"(b)); return r;
}
__device__ __forceinline__ ull fma2(ull a, ull b, ull c) {
    ull r; asm("fma.rn.f32x2 %0, %1, %2, %3;" : "=l"(r) : "l"(a), "l"(b), "l"(c)); return r;
}
__device__ __forceinline__ float ex2f(float x) {
    float r; asm("ex2.approx.f32 %0, %1;" : "=f"(r) : "f"(x)); return r;
}
#define ABS2 0x7FFFFFFF7FFFFFFFULL
#define L2E  1.4426950408889634f
#define LINR 1.5316455696f           // 0.605 / 0.395

// attn-phase smem layout (float offsets):
#define OFF_GL   0
#define OFF_GR   (NN * GLS)                    // 18432
#define OFF_AT   (OFF_GR + NN * GRS)           // 36864
#define OFF_SL   (OFF_AT + NN * ATS)           // 55296
#define OFF_SR   (OFF_SL + NN)                 // 55808
#define OFF_SINV (OFF_SR + ITILE)              // 55840
#define OFF_MASK (OFF_SINV + ITILE)            // 55872
#define OFF_WB   (OFF_MASK + ITILE * 16)       // 56384
#define SMEM_FLOATS (OFF_WB + 32)              // 56416
#define SMEM_BYTES  (SMEM_FLOATS * 4)          // 225664

// GEMM-phase smem (overlaps attn region; dead until the barrier):
#define AS_STRIDE 132                          // transposed A row (128 + pad), 16B-aligned rows
#define AS_BUF    (16 * AS_STRIDE)             // 2112
#define BS_STRIDE 68
#define BS_BUF    (16 * BS_STRIDE)             // 1088

// ---------------------------------------------------------------------------
// Fused persistent kernel, 512 threads:
// phase 0: GEMM g = [h@W_l | h@W_r] -> g_scratch (128 CTAs x 128x64 tiles)
// global ticket barrier
// phase 1: GATv2 attention (R10-proven 512-thread form)
// ---------------------------------------------------------------------------
__global__ __launch_bounds__(512, 1)
void fused_kernel(const float* __restrict__ hmat,
                  const int* __restrict__ adj,
                  const float* __restrict__ W_l,
                  const float* __restrict__ W_r,
                  const float* __restrict__ attn_w,
                  float* __restrict__ out) {
    extern __shared__ float sm[];

    const int tid  = threadIdx.x;
    const int lane = tid & 31;
    const int warp = tid >> 5;                 // 0..15

    // ======================= phase 0: GEMM =======================
    {
        const int mt = blockIdx.x >> 3;        // 0..15
        const int nt = blockIdx.x & 7;         // 0..7
        const float* Bm = (nt < 4) ? W_l : W_r;
        const int bn0 = (nt & 3) * 64;
        const int outc = (nt < 4) ? bn0 : 256 + bn0;
        const int m0 = mt * 128;

        float* As  = sm;                       // 2 * 2112 floats
        float* Bsm = sm + 2 * AS_BUF;          // 2 * 1088 floats

        const int arow = tid & 127;            // 0..127
        const int acol = (tid >> 7) * 4;       // 0,4,8,12
        const int brow = tid >> 5;             // 0..15
        const int bcol = (lane) * 2;           // 0..62
        const int tx = tid & 15;               // N quad
        const int ty = tid >> 4;               // 0..31, M quad

        const float* Aptr = hmat + (size_t)(m0 + arow) * FIN + acol;
        const float* Bptr = Bm + (size_t)brow * HF + bn0 + bcol;

        ull cc[4][2] = {};

        float4 av = *(const float4*)Aptr;
        float2 bv = *(const float2*)Bptr;

#pragma unroll 1
        for (int s = 0; s < 16; s++) {
            const int buf = s & 1;
            float* asb = As + buf * AS_BUF;
            float* bsb = Bsm + buf * BS_BUF;
            // transposed A store: As[k][m], consecutive m across lanes
            asb[(acol + 0) * AS_STRIDE + arow] = av.x;
            asb[(acol + 1) * AS_STRIDE + arow] = av.y;
            asb[(acol + 2) * AS_STRIDE + arow] = av.z;
            asb[(acol + 3) * AS_STRIDE + arow] = av.w;
            *(float2*)&bsb[brow * BS_STRIDE + bcol] = bv;
            __syncthreads();
            if (s < 15) {
                av = *(const float4*)(Aptr + (s + 1) * 16);
                bv = *(const float2*)(Bptr + (size_t)(s + 1) * 16 * HF);
            }
#pragma unroll
            for (int k = 0; k < 16; k++) {
                const ulonglong2 b2 = *(const ulonglong2*)&bsb[k * BS_STRIDE + tx * 4];
                const float4 a4 = *(const float4*)&asb[k * AS_STRIDE + ty * 4];
                const ull p0 = pack2(a4.x, a4.x);
                const ull p1 = pack2(a4.y, a4.y);
                const ull p2 = pack2(a4.z, a4.z);
                const ull p3 = pack2(a4.w, a4.w);
                cc[0][0] = fma2(p0, b2.x, cc[0][0]); cc[0][1] = fma2(p0, b2.y, cc[0][1]);
                cc[1][0] = fma2(p1, b2.x, cc[1][0]); cc[1][1] = fma2(p1, b2.y, cc[1][1]);
                cc[2][0] = fma2(p2, b2.x, cc[2][0]); cc[2][1] = fma2(p2, b2.y, cc[2][1]);
                cc[3][0] = fma2(p3, b2.x, cc[3][0]); cc[3][1] = fma2(p3, b2.y, cc[3][1]);
            }
            __syncthreads();
        }

        float* C = g_scratch + (size_t)(m0 + ty * 4) * 512 + outc + tx * 4;
#pragma unroll
        for (int r = 0; r < 4; r++) {
            ulonglong2 v; v.x = cc[r][0]; v.y = cc[r][1];
            *(ulonglong2*)(C + (size_t)r * 512) = v;
        }
    }

    // ======================= global barrier =======================
    __syncthreads();
    if (tid == 0) {
        __threadfence();                       // publish this CTA's tile
        const unsigned t = atomicAdd(&g_ctr, 1u);
        const unsigned target = (t & ~127u) + 128u;
        unsigned v;
        do {
            asm volatile("ld.acquire.gpu.u32 %0, [%1];"
                         : "=r"(v) : "l"(&g_ctr) : "memory");
        } while ((int)(v - target) < 0);
    }
    __syncthreads();

    // ======================= phase 1: attention (R10 form) =======================
    float* gl_s  = sm + OFF_GL;
    float* gr_s  = sm + OFF_GR;
    float* at_s  = sm + OFF_AT;
    float* Sl_s  = sm + OFF_SL;
    float* Sr_s  = sm + OFF_SR;
    float* sinv  = sm + OFF_SINV;
    unsigned* mask_s = (unsigned*)(sm + OFF_MASK);   // [32 rows][16 words]
    ull*   wb_s  = (ull*)(sm + OFF_WB);              // 16 packed wb pairs

    const int bh = blockIdx.x >> 2;            // 0..31
    const int b  = bh >> 3;
    const int h  = bh & 7;

    // ---- packed weights into smem: wb = 0.395 * log2e * w ----
    if (tid < 16) {
        const float w0 = __ldg(attn_w + 2 * tid);
        const float w1 = __ldg(attn_w + 2 * tid + 1);
        wb_s[tid] = pack2(0.395f * L2E * w0, 0.395f * L2E * w1);
    }

    // ---- stage g_l / g_r slices once per CTA ----
    const float* gbase = g_scratch + ((size_t)b * NN) * 512 + h * NF;
#pragma unroll
    for (int it = 0; it < 8; it++) {
        const int idx = it * 512 + tid;        // 0..4095
        const int j = idx >> 3;
        const int q = (idx & 7) << 2;
        const float* gp = gbase + (size_t)j * 512 + q;
        const float4 v = *(const float4*)gp;
        const float4 u = *(const float4*)(gp + 256);
        *(float4*)(gl_s + j * GLS + q) = v;
        *(float4*)(gr_s + j * GRS + q) = u;
    }
    __syncthreads();

    // ---- Sl[j] once per CTA (one j per thread) ----
    {
        const int j = tid;
        const ull* glp = (const ull*)(gl_s + j * GLS);
        ull acc = 0;
#pragma unroll
        for (int p = 0; p < 16; p++) acc = fma2(wb_s[p], glp[p], acc);
        float lo, hi; unpack2(acc, lo, hi);
        Sl_s[j] = LINR * (lo + hi);
    }

    // =========================== item loop ===========================
#pragma unroll 1
    for (int item = 0; item < 4; item++) {
        const int blk = (blockIdx.x & 3) * 4 + item;
        const int i0 = blk * ITILE;

        // ---- adj -> bitmask (one word per thread) ----
        {
            const int row = tid >> 4;          // 0..31
            const int chunk = tid & 15;        // 0..15
            const int4* ap = (const int4*)(adj + (size_t)(i0 + row) * NN + chunk * 32);
            unsigned w = 0;
#pragma unroll
            for (int k = 0; k < 8; k++) {
                const int4 v = ap[k];
                unsigned nib = (v.x != 0) | ((v.y != 0) << 1) |
                               ((v.z != 0) << 2) | ((v.w != 0) << 3);
                w |= nib << (4 * k);
            }
            mask_s[tid] = w;
        }

        // ---- Sr for these rows ----
        if (tid < ITILE) {
            const ull* grp = (const ull*)(gr_s + (i0 + tid) * GRS);
            ull acc = 0;
#pragma unroll
            for (int p = 0; p < 16; p++) acc = fma2(wb_s[p], grp[p], acc);
            float lo, hi; unpack2(acc, lo, hi);
            Sr_s[tid] = LINR * (lo + hi);
        }
        __syncthreads();

        // ---- pass 1: scores + exp2 + row sums (warp w: rows 2w, 2w+1) ----
        {
            const int r0 = warp * 2;
            ull gri0[16], gri1[16];
            {
                const ull* ga = (const ull*)(gr_s + (i0 + r0) * GRS);
                const ull* gb = (const ull*)(gr_s + (i0 + r0 + 1) * GRS);
#pragma unroll
                for (int p = 0; p < 16; p++) { gri0[p] = ga[p]; gri1[p] = gb[p]; }
            }
            const float Sr0 = Sr_s[r0];
            const float Sr1 = Sr_s[r0 + 1];
            const unsigned* mr0 = mask_s + (r0) * 16;
            const unsigned* mr1 = mask_s + (r0 + 1) * 16;
            const ulonglong2* wvp = (const ulonglong2*)wb_s;
            float sum0 = 0.f, sum1 = 0.f;

#pragma unroll 2
            for (int jj = 0; jj < 16; jj++) {
                const int j = (jj << 5) + lane;
                const ulonglong2* glp = (const ulonglong2*)(gl_s + j * GLS);
                ulonglong2 gv = glp[0];
                const float slj = Sl_s[j];
                const unsigned w0 = mr0[jj], w1 = mr1[jj];

                ull a00 = 0, a01 = 0, a10 = 0, a11 = 0;
#pragma unroll
                for (int q = 0; q < 8; q++) {
                    ulonglong2 gvn;
                    if (q < 7) gvn = glp[q + 1];      // prefetch next
                    const ulonglong2 wv = wvp[q];
                    const int p0 = 2 * q, p1 = 2 * q + 1;
                    const ull t00 = add2(gv.x, gri0[p0]);
                    const ull t01 = add2(gv.y, gri0[p1]);
                    const ull t10 = add2(gv.x, gri1[p0]);
                    const ull t11 = add2(gv.y, gri1[p1]);
                    a00 = fma2(wv.x, t00 & ABS2, a00);
                    a01 = fma2(wv.y, t01 & ABS2, a01);
                    a10 = fma2(wv.x, t10 & ABS2, a10);
                    a11 = fma2(wv.y, t11 & ABS2, a11);
                    if (q < 7) gv = gvn;
                }
                float2 pv;
                {
                    float lo, hi; unpack2(add2(a00, a01), lo, hi);
                    const float p = ex2f(slj + Sr0 + (lo + hi));
                    pv.x = ((w0 >> lane) & 1) ? p : 0.f; sum0 += pv.x;
                }
                {
                    float lo, hi; unpack2(add2(a10, a11), lo, hi);
                    const float p = ex2f(slj + Sr1 + (lo + hi));
                    pv.y = ((w1 >> lane) & 1) ? p : 0.f; sum1 += pv.y;
                }
                *(float2*)(at_s + j * ATS + r0) = pv;
            }
#pragma unroll
            for (int o = 16; o; o >>= 1) {
                sum0 += __shfl_xor_sync(0xffffffffu, sum0, o);
                sum1 += __shfl_xor_sync(0xffffffffu, sum1, o);
            }
            if (lane == 0) {
                sinv[r0 + 0] = 1.0f / sum0;
                sinv[r0 + 1] = 1.0f / sum1;
            }
        }
        __syncthreads();

        // ---- pass 2: partials into warp's own at_s slice (16 warps x 32 j) ----
        {
            const int fq = tid & 7;
            const int ig = (tid >> 3) & 3;
            const int jq = warp;
            ull acc[4][4] = {};                // [i-pair][f]
            const int jbeg = jq * 32;
#pragma unroll 4
            for (int jo = 0; jo < 32; jo++) {
                const int j = jbeg + jo;
                const float4 g4 = *(const float4*)(gr_s + j * GRS + fq * 4);
                const ull pg0 = pack2(g4.x, g4.x);
                const ull pg1 = pack2(g4.y, g4.y);
                const ull pg2 = pack2(g4.z, g4.z);
                const ull pg3 = pack2(g4.w, g4.w);
                const ull* ap = (const ull*)(at_s + j * ATS + ig * 8);
#pragma unroll
                for (int p = 0; p < 4; p++) {
                    const ull a = ap[p];
                    acc[p][0] = fma2(a, pg0, acc[p][0]);
                    acc[p][1] = fma2(a, pg1, acc[p][1]);
                    acc[p][2] = fma2(a, pg2, acc[p][2]);
                    acc[p][3] = fma2(a, pg3, acc[p][3]);
                }
            }
            // warp-local slab at the head of its own 32-row j-slice
            ull* part = (ull*)(at_s + jq * 32 * ATS);
#pragma unroll
            for (int p = 0; p < 4; p++) {
#pragma unroll
                for (int k = 0; k < 4; k++)
                    part[(ig * 4 + p) * 32 + fq * 4 + k] = acc[p][k];
            }
        }
        __syncthreads();

        // ---- final reduce over 16 slabs + scale + store (1 f per thread) ----
        {
            const int ip = tid >> 5;           // 0..15 (i-pair)
            const int f  = tid & 31;
            const ull* base = (const ull*)at_s;
            ull u = 0;
#pragma unroll
            for (int q = 0; q < 16; q++)
                u = add2(u, base[(size_t)q * (32 * ATS / 2) + ip * 32 + f]);
            float lo, hi; unpack2(u, lo, hi);
            const int il = ip * 2;
            float* op = out + ((size_t)(b * NN + i0 + il)) * HF + h * NF + f;
            op[0]  = lo * sinv[il];
            op[HF] = hi * sinv[il + 1];
        }
        __syncthreads();
    }
}

// ---------------------------------------------------------------------------
extern "C" void kernel_launch(void* const* d_in, const int* in_sizes, int n_in,
                              void* d_out, int out_size) {
    (void)in_sizes; (void)n_in; (void)out_size;
    const float* h      = (const float*)d_in[0];
    const int*   adj    = (const int*)  d_in[1];
    const float* W_l    = (const float*)d_in[2];
    const float* W_r    = (const float*)d_in[3];
    const float* attn_w = (const float*)d_in[4];
    float* out = (float*)d_out;

    cudaFuncSetAttribute(fused_kernel,
                         cudaFuncAttributeMaxDynamicSharedMemorySize, SMEM_BYTES);

    fused_kernel<<<128, 512, SMEM_BYTES>>>(h, adj, W_l, W_r, attn_w, out);
}